// round 16
// baseline (speedup 1.0000x reference)
#include <cuda_runtime.h>
#include <math.h>

// ---------------------------------------------------------------------------
// Scratch accumulators (__device__ globals, zero-initialized at load; the
// finalizing block resets them so every graph replay starts from zeros).
// ---------------------------------------------------------------------------
__device__ double       g_seg = 0.0;            // seg BCE raw sum
__device__ float        g_det[3][32][4];        // per scale/image: cls,reg,cen,npos
__device__ float        g_cls = 0.0f;           // cls focal raw sum
__device__ unsigned int g_count = 0u;           // block arrival counter

// ---------------------------------------------------------------------------
// Packed f32x2 helpers (Blackwell dual-lane f32; PTX-only)
// ---------------------------------------------------------------------------
typedef unsigned long long u64;

__device__ __forceinline__ u64 pack2(float lo, float hi) {
    u64 r;
    asm("mov.b64 %0, {%1, %2};" : "=l"(r) : "f"(lo), "f"(hi));
    return r;
}
__device__ __forceinline__ void unpack2(u64 v, float& lo, float& hi) {
    asm("mov.b64 {%0, %1}, %2;" : "=f"(lo), "=f"(hi) : "l"(v));
}
__device__ __forceinline__ u64 fma2(u64 a, u64 b, u64 c) {
    u64 d;
    asm("fma.rn.f32x2 %0, %1, %2, %3;" : "=l"(d) : "l"(a), "l"(b), "l"(c));
    return d;
}
__device__ __forceinline__ u64 add2(u64 a, u64 b) {
    u64 d;
    asm("add.rn.f32x2 %0, %1, %2;" : "=l"(d) : "l"(a), "l"(b));
    return d;
}
// L2 prefetch: no register, no scoreboard; invalid addresses are ignored.
__device__ __forceinline__ void prefetch_l2(const void* p) {
    asm volatile("prefetch.global.L2 [%0];" :: "l"(p));
}

// log1p(e) for e in [0,1]:
// deg-4 (HW-validated rel_err 7e-7) — used on det/cls paths.
#define LQ4_C4 (-0.05546112f)
#define LQ4_C3 ( 0.21867176f)
#define LQ4_C2 (-0.46644868f)
#define LQ4_C1 ( 0.99626390f)
#define LQ4_C0 ( 0.00007393f)
// deg-3 = Chebyshev economization of deg-4 (±4.3e-4, HW-validated rel_err 2e-6)
// — used on the bulk seg path.
#define LQ3_C3 ( 0.10774952f)
#define LQ3_C2 (-0.39712228f)
#define LQ3_C1 ( 0.98239862f)
#define LQ3_C0 ( 0.00050722f)

__device__ __forceinline__ float log1p_poly4(float e) {
    float p = LQ4_C4;
    p = fmaf(p, e, LQ4_C3);
    p = fmaf(p, e, LQ4_C2);
    p = fmaf(p, e, LQ4_C1);
    p = fmaf(p, e, LQ4_C0);
    return p;
}

// ---------------------------------------------------------------------------
// Scalar math helpers (det / cls paths)
// ---------------------------------------------------------------------------
__device__ __forceinline__ float bce_f(float x, float y) {
    float e = __expf(-fabsf(x));
    return fmaxf(x, 0.0f) - x * y + log1p_poly4(e);
}

__device__ __forceinline__ float focal_el(float x, bool t1) {
    float e   = __expf(-fabsf(x));
    float l1p = log1p_poly4(e);
    float d   = __fdividef(1.0f, 1.0f + e);
    float sig = (x >= 0.0f) ? d : e * d;  // sigmoid(x)
    if (t1) {
        float om = 1.0f - sig;
        float sp = fmaxf(-x, 0.0f) + l1p;  // bce(x,1)
        return 0.25f * om * om * sp;
    } else {
        float sp = fmaxf(x, 0.0f) + l1p;   // bce(x,0)
        return 0.75f * sig * sig * sp;
    }
}

// Block reduction; result valid on thread 0.
__device__ __forceinline__ float block_reduce(float v, float* sh) {
    int lane = threadIdx.x & 31;
    int wid  = threadIdx.x >> 5;
    #pragma unroll
    for (int o = 16; o; o >>= 1) v += __shfl_down_sync(0xffffffffu, v, o);
    if (lane == 0) sh[wid] = v;
    __syncthreads();
    int nw = (blockDim.x + 31) >> 5;
    v = (threadIdx.x < nw) ? sh[threadIdx.x] : 0.0f;
    if (wid == 0) {
        #pragma unroll
        for (int o = 16; o; o >>= 1) v += __shfl_down_sync(0xffffffffu, v, o);
    }
    __syncthreads();
    return v;
}

// ---------------------------------------------------------------------------
// Seg per-channel accumulation (4 elements), degree-3 packed poly.
// ---------------------------------------------------------------------------
__device__ __forceinline__ void seg_channel(
    float4 x, float hy0, float hy1, float hy2, float hy3,
    u64 C3, u64 C2, u64 C1, u64 C0,
    float& acc_s, u64& acc2a, u64& acc2b)
{
    float e0 = __expf(-fabsf(x.x));
    float e1 = __expf(-fabsf(x.y));
    float e2 = __expf(-fabsf(x.z));
    float e3 = __expf(-fabsf(x.w));

    acc_s = fmaf(x.x, hy0, acc_s);  acc_s = fmaf(fabsf(x.x), 0.5f, acc_s);
    acc_s = fmaf(x.y, hy1, acc_s);  acc_s = fmaf(fabsf(x.y), 0.5f, acc_s);
    acc_s = fmaf(x.z, hy2, acc_s);  acc_s = fmaf(fabsf(x.z), 0.5f, acc_s);
    acc_s = fmaf(x.w, hy3, acc_s);  acc_s = fmaf(fabsf(x.w), 0.5f, acc_s);

    u64 E = pack2(e0, e1);
    u64 p = fma2(C3, E, C2);
    p = fma2(p, E, C1);
    p = fma2(p, E, C0);
    acc2a = add2(acc2a, p);

    E = pack2(e2, e3);
    p = fma2(C3, E, C2);
    p = fma2(p, E, C1);
    p = fma2(p, E, C0);
    acc2b = add2(acc2b, p);
}

// ---------------------------------------------------------------------------
// Detection chunk: one block handles 256 locations of (scale, image b).
// ---------------------------------------------------------------------------
template <int STRIDE, int HWDIM, int SCALE>
__device__ void det_chunk(int b, int chunk,
                          const float* __restrict__ cls,
                          const float* __restrict__ reg,
                          const float* __restrict__ cent,
                          const float* __restrict__ boxes,
                          const int*   __restrict__ labels,
                          float* sh) {
    const int NB = 20;
    const int L  = HWDIM * HWDIM;

    __shared__ float sx0[NB], sy0[NB], sx1[NB], sy1[NB], sa[NB];
    __shared__ int   slab[NB];
    if (threadIdx.x < NB) {
        int j = threadIdx.x;
        const float* bp = boxes + ((long long)b * NB + j) * 4;
        float cx = bp[0] * 512.0f, cy = bp[1] * 512.0f;
        float w  = bp[2] * 512.0f, h  = bp[3] * 512.0f;
        float x0 = cx - w * 0.5f, y0 = cy - h * 0.5f;
        float x1 = cx + w * 0.5f, y1 = cy + h * 0.5f;
        sx0[j] = x0; sy0[j] = y0; sx1[j] = x1; sy1[j] = y1;
        sa[j]  = (x1 - x0) * (y1 - y0);
        slab[j] = labels[b * NB + j];
    }
    __syncthreads();

    const int l  = chunk * 256 + threadIdx.x;   // location index (always < L)
    const int hh = l / HWDIM, ww = l - hh * HWDIM;
    const float lx = (ww + 0.5f) * (float)STRIDE;
    const float ly = (hh + 0.5f) * (float)STRIDE;
    const float inv_stride = 1.0f / (float)STRIDE;

    float best_a = INFINITY;
    int   best   = 0;
    bool  pos    = false;
    #pragma unroll 5
    for (int j = 0; j < NB; j++) {
        float l_ = lx - sx0[j];
        float t_ = ly - sy0[j];
        float r_ = sx1[j] - lx;
        float m_ = sy1[j] - ly;
        float mn = fminf(fminf(l_, t_), fminf(r_, m_));
        bool ins = mn > 0.0f;
        pos = pos || ins;
        float a = ins ? sa[j] : INFINITY;
        if (a < best_a) { best_a = a; best = j; }   // strict < = first-min
    }

    float rt0 = (lx - sx0[best]) * inv_stride;
    float rt1 = (ly - sy0[best]) * inv_stride;
    float rt2 = (sx1[best] - lx) * inv_stride;
    float rt3 = (sy1[best] - ly) * inv_stride;
    int label = pos ? slab[best] : -1;

    float cls_sum = 0.0f;
    #pragma unroll
    for (int c = 0; c < 4; c++) {
        float x = cls[((long long)b * 5 + (c + 1)) * L + l];
        cls_sum += focal_el(x, c == label);
    }

    float reg_sum = 0.0f, cen_sum = 0.0f, npos_f = 0.0f;
    if (pos) {
        float rt[4] = {rt0, rt1, rt2, rt3};
        float sl1 = 0.0f;
        #pragma unroll
        for (int c = 0; c < 4; c++) {
            float d  = reg[((long long)b * 4 + c) * L + l] - rt[c];
            float ad = fabsf(d);
            sl1 += (ad < 1.0f) ? 0.5f * d * d : ad - 0.5f;
        }
        reg_sum = sl1 * 0.25f;

        const float eps = 1e-6f;
        float mnlr = fminf(rt0, rt2), mxlr = fmaxf(rt0, rt2);
        float mntb = fminf(rt1, rt3), mxtb = fmaxf(rt1, rt3);
        float v = __fdividef(mnlr, mxlr + eps) * __fdividef(mntb, mxtb + eps);
        v = fminf(fmaxf(v, 0.0f), 1.0f);
        cen_sum = bce_f(cent[(long long)b * L + l], sqrtf(v));
        npos_f  = 1.0f;
    }

    float ct  = block_reduce(cls_sum, sh);
    float rt_ = block_reduce(reg_sum, sh);
    float ce  = block_reduce(cen_sum, sh);
    float np  = block_reduce(npos_f,  sh);
    if (threadIdx.x == 0) {
        atomicAdd(&g_det[SCALE][b][0], ct);
        atomicAdd(&g_det[SCALE][b][1], rt_);
        atomicAdd(&g_det[SCALE][b][2], ce);
        atomicAdd(&g_det[SCALE][b][3], np);
    }
}

// ---------------------------------------------------------------------------
// Block layout (special blocks FIRST; seg blocks backfill behind them)
// Grid = 3552 = 4 exact waves at 148 SMs * 6 blocks.
// ---------------------------------------------------------------------------
static const int DET0_B = 512, DET1_B = 128, DET2_B = 32;
static const int CLS_BID = DET0_B + DET1_B + DET2_B;   // 672
static const int TOTAL_BLOCKS = 3552;                   // 4 waves @ occ 6
static const int NSEG = TOTAL_BLOCKS - CLS_BID - 1;     // 2879

__global__ void __launch_bounds__(256, 6)
main_kernel(const float* __restrict__ seg_logits,
            const int*   __restrict__ seg_mask,
            const float* __restrict__ cls_s0,
            const float* __restrict__ cls_s1,
            const float* __restrict__ cls_s2,
            const float* __restrict__ reg_s0,
            const float* __restrict__ reg_s1,
            const float* __restrict__ reg_s2,
            const float* __restrict__ cen_s0,
            const float* __restrict__ cen_s1,
            const float* __restrict__ cen_s2,
            const float* __restrict__ boxes,
            const int*   __restrict__ labels,
            const float* __restrict__ cls_pred,
            const int*   __restrict__ cls_target,
            float* __restrict__ out, int out_n) {
    __shared__ float sh[32];
    const int bid = blockIdx.x;

    if (bid < DET0_B) {
        det_chunk<8, 64, 0>(bid >> 4, bid & 15, cls_s0, reg_s0, cen_s0, boxes, labels, sh);
    } else if (bid < DET0_B + DET1_B) {
        int x = bid - DET0_B;
        det_chunk<16, 32, 1>(x >> 2, x & 3, cls_s1, reg_s1, cen_s1, boxes, labels, sh);
    } else if (bid < CLS_BID) {
        int x = bid - DET0_B - DET1_B;
        det_chunk<32, 16, 2>(x, 0, cls_s2, reg_s2, cen_s2, boxes, labels, sh);
    } else if (bid == CLS_BID) {
        float v = 0.0f;
        for (int i = threadIdx.x; i < 320; i += blockDim.x) {
            int bb = i / 10, cc = i - bb * 10;
            v += focal_el(cls_pred[i], cls_target[bb] == cc);
        }
        float s = block_reduce(v, sh);
        if (threadIdx.x == 0) atomicAdd(&g_cls, s);
    } else {
        // ---- segmentation BCE: (32,4,512,512) logits vs broadcast mask ----
        const unsigned HW   = 512u * 512u;          // 2^18
        const unsigned NVEC = (32u * HW) >> 2;      // float4 groups: 2^23
        const unsigned stride = (unsigned)NSEG * 256u;

        const u64 C3 = pack2(LQ3_C3, LQ3_C3);
        const u64 C2 = pack2(LQ3_C2, LQ3_C2);
        const u64 C1 = pack2(LQ3_C1, LQ3_C1);
        const u64 C0 = pack2(LQ3_C0, LQ3_C0);

        float acc_s = 0.0f;
        u64   acc2a = pack2(0.0f, 0.0f);
        u64   acc2b = pack2(0.0f, 0.0f);

        const unsigned v0 = (unsigned)(bid - CLS_BID - 1) * 256u + threadIdx.x;

        // Prologue: cover iteration 2's window (distance-1 prefetch, once).
        {
            unsigned vp = v0 + stride;
            if (vp < NVEC) {
                unsigned sp  = vp << 2;
                unsigned bp  = sp >> 18;
                unsigned hwp = sp & (HW - 1u);
                const float* lpp = seg_logits + (bp * 4u) * HW + hwp;
                prefetch_l2(seg_mask + bp * HW + hwp);
                prefetch_l2(lpp);
                prefetch_l2(lpp + HW);
                prefetch_l2(lpp + 2u * HW);
                prefetch_l2(lpp + 3u * HW);
            }
        }

        for (unsigned v = v0; v < NVEC; v += stride) {
            unsigned s  = v << 2;
            unsigned b  = s >> 18;
            unsigned hw = s & (HW - 1u);

            // current loads (streaming, read-once; L2-hits thanks to prefetch)
            int4 m = __ldcs(reinterpret_cast<const int4*>(seg_mask + b * HW + hw));
            const float* lp = seg_logits + (b * 4u) * HW + hw;
            float4 x0 = __ldcs(reinterpret_cast<const float4*>(lp));
            float4 x1 = __ldcs(reinterpret_cast<const float4*>(lp + HW));
            float4 x2 = __ldcs(reinterpret_cast<const float4*>(lp + 2u * HW));
            float4 x3 = __ldcs(reinterpret_cast<const float4*>(lp + 3u * HW));

            // Distance-2 L2 prefetch: DRAM->L2 transfer fully overlaps two
            // compute iterations, so demand loads become L2 hits.
            unsigned vn = v + 2u * stride;
            if (vn < NVEC) {
                unsigned sn  = vn << 2;
                unsigned bn  = sn >> 18;
                unsigned hwn = sn & (HW - 1u);
                const float* lpn = seg_logits + (bn * 4u) * HW + hwn;
                prefetch_l2(seg_mask + bn * HW + hwn);
                prefetch_l2(lpn);
                prefetch_l2(lpn + HW);
                prefetch_l2(lpn + 2u * HW);
                prefetch_l2(lpn + 3u * HW);
            }

            float hy0 = 0.5f - (float)m.x;
            float hy1 = 0.5f - (float)m.y;
            float hy2 = 0.5f - (float)m.z;
            float hy3 = 0.5f - (float)m.w;

            seg_channel(x0, hy0, hy1, hy2, hy3, C3, C2, C1, C0, acc_s, acc2a, acc2b);
            seg_channel(x1, hy0, hy1, hy2, hy3, C3, C2, C1, C0, acc_s, acc2a, acc2b);
            seg_channel(x2, hy0, hy1, hy2, hy3, C3, C2, C1, C0, acc_s, acc2a, acc2b);
            seg_channel(x3, hy0, hy1, hy2, hy3, C3, C2, C1, C0, acc_s, acc2a, acc2b);
        }

        u64 acc2 = add2(acc2a, acc2b);
        float plo, phi;
        unpack2(acc2, plo, phi);
        float acc = acc_s + (plo + phi);

        float bs = block_reduce(acc, sh);
        if (threadIdx.x == 0) atomicAdd(&g_seg, (double)bs);
    }

    // ---- last-block finalize + reset ----
    __shared__ int is_last;
    if (threadIdx.x == 0) {
        __threadfence();
        unsigned old = atomicAdd(&g_count, 1u);
        is_last = (old == (unsigned)(gridDim.x - 1)) ? 1 : 0;
    }
    __syncthreads();
    if (is_last) {
        const int i = threadIdx.x;
        float v = 0.0f;
        if (i < 96) {
            int s = i >> 5, b = i & 31;
            const int Ls = (s == 0) ? 4096 : (s == 1) ? 1024 : 256;
            float cs = g_det[s][b][0];
            float rs = g_det[s][b][1];
            float ce = g_det[s][b][2];
            float np = g_det[s][b][3];
            float cls_l = cs / (float)(Ls * 4);
            float reg_l = (np > 0.0f) ? rs / np : 0.0f;
            float cen_l = (np > 0.0f) ? ce / np : 0.0f;
            v = cls_l + reg_l + cen_l;
        }
        double seg_v = g_seg;
        float  cls_v = g_cls;
        __syncthreads();                  // all reads done before reset
        float det_tot = block_reduce(v, sh);

        __shared__ float res;
        if (i == 0) {
            double total = seg_v / (32.0 * 4.0 * 512.0 * 512.0)
                         + (double)det_tot / (3.0 * 32.0)
                         + 0.5 * (double)cls_v / 320.0;
            res = (float)total;
            g_seg = 0.0; g_cls = 0.0f; g_count = 0u;
        }
        for (int k = i; k < 3 * 32 * 4; k += blockDim.x)
            (&g_det[0][0][0])[k] = 0.0f;
        __syncthreads();
        for (int k = i; k < out_n; k += blockDim.x) out[k] = res;
    }
}

// ---------------------------------------------------------------------------
// Launch: single kernel node.
// ---------------------------------------------------------------------------
extern "C" void kernel_launch(void* const* d_in, const int* in_sizes, int n_in,
                              void* d_out, int out_size) {
    main_kernel<<<TOTAL_BLOCKS, 256>>>(
        (const float*)d_in[0],  (const int*)d_in[1],
        (const float*)d_in[2],  (const float*)d_in[3],  (const float*)d_in[4],
        (const float*)d_in[5],  (const float*)d_in[6],  (const float*)d_in[7],
        (const float*)d_in[8],  (const float*)d_in[9],  (const float*)d_in[10],
        (const float*)d_in[11], (const int*)d_in[12],
        (const float*)d_in[13], (const int*)d_in[14],
        (float*)d_out, out_size);
}

// round 17
// speedup vs baseline: 1.0620x; 1.0620x over previous
#include <cuda_runtime.h>
#include <math.h>

// ---------------------------------------------------------------------------
// Scratch accumulators (__device__ globals, zero-initialized at load; the
// finalizing block resets them so every graph replay starts from zeros).
// ---------------------------------------------------------------------------
__device__ double       g_seg = 0.0;            // seg BCE raw sum
__device__ float        g_det[3][32][4];        // per scale/image: cls,reg,cen,npos
__device__ float        g_cls = 0.0f;           // cls focal raw sum
__device__ unsigned int g_count = 0u;           // block arrival counter

// ---------------------------------------------------------------------------
// Packed f32x2 helpers (Blackwell dual-lane f32; PTX-only)
// ---------------------------------------------------------------------------
typedef unsigned long long u64;

__device__ __forceinline__ u64 pack2(float lo, float hi) {
    u64 r;
    asm("mov.b64 %0, {%1, %2};" : "=l"(r) : "f"(lo), "f"(hi));
    return r;
}
__device__ __forceinline__ void unpack2(u64 v, float& lo, float& hi) {
    asm("mov.b64 {%0, %1}, %2;" : "=f"(lo), "=f"(hi) : "l"(v));
}
__device__ __forceinline__ u64 fma2(u64 a, u64 b, u64 c) {
    u64 d;
    asm("fma.rn.f32x2 %0, %1, %2, %3;" : "=l"(d) : "l"(a), "l"(b), "l"(c));
    return d;
}
__device__ __forceinline__ u64 add2(u64 a, u64 b) {
    u64 d;
    asm("add.rn.f32x2 %0, %1, %2;" : "=l"(d) : "l"(a), "l"(b));
    return d;
}
// Bulk L2 prefetch: ONE instruction pulls `bytes` (16B-multiple) into L2.
// No destination, no mbarrier, no register result.
__device__ __forceinline__ void bulk_prefetch_l2(const void* p, unsigned bytes) {
    asm volatile("cp.async.bulk.prefetch.L2.global [%0], %1;"
                 :: "l"(p), "r"(bytes) : "memory");
}

// log1p(e) for e in [0,1]:
// deg-4 (HW-validated rel_err 7e-7) — used on det/cls paths.
#define LQ4_C4 (-0.05546112f)
#define LQ4_C3 ( 0.21867176f)
#define LQ4_C2 (-0.46644868f)
#define LQ4_C1 ( 0.99626390f)
#define LQ4_C0 ( 0.00007393f)
// deg-3 = Chebyshev economization of deg-4 (±4.3e-4, HW-validated rel_err 2e-6)
// — used on the bulk seg path.
#define LQ3_C3 ( 0.10774952f)
#define LQ3_C2 (-0.39712228f)
#define LQ3_C1 ( 0.98239862f)
#define LQ3_C0 ( 0.00050722f)

__device__ __forceinline__ float log1p_poly4(float e) {
    float p = LQ4_C4;
    p = fmaf(p, e, LQ4_C3);
    p = fmaf(p, e, LQ4_C2);
    p = fmaf(p, e, LQ4_C1);
    p = fmaf(p, e, LQ4_C0);
    return p;
}

// ---------------------------------------------------------------------------
// Scalar math helpers (det / cls paths)
// ---------------------------------------------------------------------------
__device__ __forceinline__ float bce_f(float x, float y) {
    float e = __expf(-fabsf(x));
    return fmaxf(x, 0.0f) - x * y + log1p_poly4(e);
}

__device__ __forceinline__ float focal_el(float x, bool t1) {
    float e   = __expf(-fabsf(x));
    float l1p = log1p_poly4(e);
    float d   = __fdividef(1.0f, 1.0f + e);
    float sig = (x >= 0.0f) ? d : e * d;  // sigmoid(x)
    if (t1) {
        float om = 1.0f - sig;
        float sp = fmaxf(-x, 0.0f) + l1p;  // bce(x,1)
        return 0.25f * om * om * sp;
    } else {
        float sp = fmaxf(x, 0.0f) + l1p;   // bce(x,0)
        return 0.75f * sig * sig * sp;
    }
}

// Block reduction; result valid on thread 0.
__device__ __forceinline__ float block_reduce(float v, float* sh) {
    int lane = threadIdx.x & 31;
    int wid  = threadIdx.x >> 5;
    #pragma unroll
    for (int o = 16; o; o >>= 1) v += __shfl_down_sync(0xffffffffu, v, o);
    if (lane == 0) sh[wid] = v;
    __syncthreads();
    int nw = (blockDim.x + 31) >> 5;
    v = (threadIdx.x < nw) ? sh[threadIdx.x] : 0.0f;
    if (wid == 0) {
        #pragma unroll
        for (int o = 16; o; o >>= 1) v += __shfl_down_sync(0xffffffffu, v, o);
    }
    __syncthreads();
    return v;
}

// ---------------------------------------------------------------------------
// Seg per-channel accumulation (4 elements), degree-3 packed poly.
// ---------------------------------------------------------------------------
__device__ __forceinline__ void seg_channel(
    float4 x, float hy0, float hy1, float hy2, float hy3,
    u64 C3, u64 C2, u64 C1, u64 C0,
    float& acc_s, u64& acc2a, u64& acc2b)
{
    float e0 = __expf(-fabsf(x.x));
    float e1 = __expf(-fabsf(x.y));
    float e2 = __expf(-fabsf(x.z));
    float e3 = __expf(-fabsf(x.w));

    acc_s = fmaf(x.x, hy0, acc_s);  acc_s = fmaf(fabsf(x.x), 0.5f, acc_s);
    acc_s = fmaf(x.y, hy1, acc_s);  acc_s = fmaf(fabsf(x.y), 0.5f, acc_s);
    acc_s = fmaf(x.z, hy2, acc_s);  acc_s = fmaf(fabsf(x.z), 0.5f, acc_s);
    acc_s = fmaf(x.w, hy3, acc_s);  acc_s = fmaf(fabsf(x.w), 0.5f, acc_s);

    u64 E = pack2(e0, e1);
    u64 p = fma2(C3, E, C2);
    p = fma2(p, E, C1);
    p = fma2(p, E, C0);
    acc2a = add2(acc2a, p);

    E = pack2(e2, e3);
    p = fma2(C3, E, C2);
    p = fma2(p, E, C1);
    p = fma2(p, E, C0);
    acc2b = add2(acc2b, p);
}

// ---------------------------------------------------------------------------
// Detection chunk: one block handles 256 locations of (scale, image b).
// ---------------------------------------------------------------------------
template <int STRIDE, int HWDIM, int SCALE>
__device__ void det_chunk(int b, int chunk,
                          const float* __restrict__ cls,
                          const float* __restrict__ reg,
                          const float* __restrict__ cent,
                          const float* __restrict__ boxes,
                          const int*   __restrict__ labels,
                          float* sh) {
    const int NB = 20;
    const int L  = HWDIM * HWDIM;

    __shared__ float sx0[NB], sy0[NB], sx1[NB], sy1[NB], sa[NB];
    __shared__ int   slab[NB];
    if (threadIdx.x < NB) {
        int j = threadIdx.x;
        const float* bp = boxes + ((long long)b * NB + j) * 4;
        float cx = bp[0] * 512.0f, cy = bp[1] * 512.0f;
        float w  = bp[2] * 512.0f, h  = bp[3] * 512.0f;
        float x0 = cx - w * 0.5f, y0 = cy - h * 0.5f;
        float x1 = cx + w * 0.5f, y1 = cy + h * 0.5f;
        sx0[j] = x0; sy0[j] = y0; sx1[j] = x1; sy1[j] = y1;
        sa[j]  = (x1 - x0) * (y1 - y0);
        slab[j] = labels[b * NB + j];
    }
    __syncthreads();

    const int l  = chunk * 256 + threadIdx.x;   // location index (always < L)
    const int hh = l / HWDIM, ww = l - hh * HWDIM;
    const float lx = (ww + 0.5f) * (float)STRIDE;
    const float ly = (hh + 0.5f) * (float)STRIDE;
    const float inv_stride = 1.0f / (float)STRIDE;

    float best_a = INFINITY;
    int   best   = 0;
    bool  pos    = false;
    #pragma unroll 5
    for (int j = 0; j < NB; j++) {
        float l_ = lx - sx0[j];
        float t_ = ly - sy0[j];
        float r_ = sx1[j] - lx;
        float m_ = sy1[j] - ly;
        float mn = fminf(fminf(l_, t_), fminf(r_, m_));
        bool ins = mn > 0.0f;
        pos = pos || ins;
        float a = ins ? sa[j] : INFINITY;
        if (a < best_a) { best_a = a; best = j; }   // strict < = first-min
    }

    float rt0 = (lx - sx0[best]) * inv_stride;
    float rt1 = (ly - sy0[best]) * inv_stride;
    float rt2 = (sx1[best] - lx) * inv_stride;
    float rt3 = (sy1[best] - ly) * inv_stride;
    int label = pos ? slab[best] : -1;

    float cls_sum = 0.0f;
    #pragma unroll
    for (int c = 0; c < 4; c++) {
        float x = cls[((long long)b * 5 + (c + 1)) * L + l];
        cls_sum += focal_el(x, c == label);
    }

    float reg_sum = 0.0f, cen_sum = 0.0f, npos_f = 0.0f;
    if (pos) {
        float rt[4] = {rt0, rt1, rt2, rt3};
        float sl1 = 0.0f;
        #pragma unroll
        for (int c = 0; c < 4; c++) {
            float d  = reg[((long long)b * 4 + c) * L + l] - rt[c];
            float ad = fabsf(d);
            sl1 += (ad < 1.0f) ? 0.5f * d * d : ad - 0.5f;
        }
        reg_sum = sl1 * 0.25f;

        const float eps = 1e-6f;
        float mnlr = fminf(rt0, rt2), mxlr = fmaxf(rt0, rt2);
        float mntb = fminf(rt1, rt3), mxtb = fmaxf(rt1, rt3);
        float v = __fdividef(mnlr, mxlr + eps) * __fdividef(mntb, mxtb + eps);
        v = fminf(fmaxf(v, 0.0f), 1.0f);
        cen_sum = bce_f(cent[(long long)b * L + l], sqrtf(v));
        npos_f  = 1.0f;
    }

    float ct  = block_reduce(cls_sum, sh);
    float rt_ = block_reduce(reg_sum, sh);
    float ce  = block_reduce(cen_sum, sh);
    float np  = block_reduce(npos_f,  sh);
    if (threadIdx.x == 0) {
        atomicAdd(&g_det[SCALE][b][0], ct);
        atomicAdd(&g_det[SCALE][b][1], rt_);
        atomicAdd(&g_det[SCALE][b][2], ce);
        atomicAdd(&g_det[SCALE][b][3], np);
    }
}

// ---------------------------------------------------------------------------
// Block layout (special blocks FIRST; seg blocks backfill behind them)
// Grid = 3552 = 4 exact waves at 148 SMs * 6 blocks.
// ---------------------------------------------------------------------------
static const int DET0_B = 512, DET1_B = 128, DET2_B = 32;
static const int CLS_BID = DET0_B + DET1_B + DET2_B;   // 672
static const int TOTAL_BLOCKS = 3552;                   // 4 waves @ occ 6
static const int NSEG = TOTAL_BLOCKS - CLS_BID - 1;     // 2879

__global__ void __launch_bounds__(256, 6)
main_kernel(const float* __restrict__ seg_logits,
            const int*   __restrict__ seg_mask,
            const float* __restrict__ cls_s0,
            const float* __restrict__ cls_s1,
            const float* __restrict__ cls_s2,
            const float* __restrict__ reg_s0,
            const float* __restrict__ reg_s1,
            const float* __restrict__ reg_s2,
            const float* __restrict__ cen_s0,
            const float* __restrict__ cen_s1,
            const float* __restrict__ cen_s2,
            const float* __restrict__ boxes,
            const int*   __restrict__ labels,
            const float* __restrict__ cls_pred,
            const int*   __restrict__ cls_target,
            float* __restrict__ out, int out_n) {
    __shared__ float sh[32];
    const int bid = blockIdx.x;

    if (bid < DET0_B) {
        det_chunk<8, 64, 0>(bid >> 4, bid & 15, cls_s0, reg_s0, cen_s0, boxes, labels, sh);
    } else if (bid < DET0_B + DET1_B) {
        int x = bid - DET0_B;
        det_chunk<16, 32, 1>(x >> 2, x & 3, cls_s1, reg_s1, cen_s1, boxes, labels, sh);
    } else if (bid < CLS_BID) {
        int x = bid - DET0_B - DET1_B;
        det_chunk<32, 16, 2>(x, 0, cls_s2, reg_s2, cen_s2, boxes, labels, sh);
    } else if (bid == CLS_BID) {
        float v = 0.0f;
        for (int i = threadIdx.x; i < 320; i += blockDim.x) {
            int bb = i / 10, cc = i - bb * 10;
            v += focal_el(cls_pred[i], cls_target[bb] == cc);
        }
        float s = block_reduce(v, sh);
        if (threadIdx.x == 0) atomicAdd(&g_cls, s);
    } else {
        // ---- segmentation BCE: (32,4,512,512) logits vs broadcast mask ----
        // Each block-iteration consumes 5 contiguous 4KB chunks (mask + 4
        // channels). Thread 0 bulk-prefetches NEXT iteration's 5 chunks into
        // L2 (distance-1: ~59MB chip-wide in flight, fits the ~126MB L2);
        // demand __ldcs loads then hit L2 instead of DRAM.
        const unsigned HW   = 512u * 512u;          // 2^18
        const unsigned NVEC = (32u * HW) >> 2;      // float4 groups: 2^23
        const unsigned stride = (unsigned)NSEG * 256u;

        const u64 C3 = pack2(LQ3_C3, LQ3_C3);
        const u64 C2 = pack2(LQ3_C2, LQ3_C2);
        const u64 C1 = pack2(LQ3_C1, LQ3_C1);
        const u64 C0 = pack2(LQ3_C0, LQ3_C0);

        float acc_s = 0.0f;
        u64   acc2a = pack2(0.0f, 0.0f);
        u64   acc2b = pack2(0.0f, 0.0f);

        const unsigned v0 = (unsigned)(bid - CLS_BID - 1) * 256u + threadIdx.x;

        // Prologue (thread 0): bulk-prefetch this block's FIRST chunks so the
        // demand loads of iteration 0 already overlap DRAM->L2 transfer.
        if (threadIdx.x == 0 && v0 < NVEC) {
            unsigned sb  = v0 << 2;                 // tid==0 -> block base
            unsigned bb  = sb >> 18;
            unsigned hwb = sb & (HW - 1u);
            const float* lpb = seg_logits + (bb * 4u) * HW + hwb;
            bulk_prefetch_l2(seg_mask + bb * HW + hwb, 4096u);
            bulk_prefetch_l2(lpb,            4096u);
            bulk_prefetch_l2(lpb + HW,       4096u);
            bulk_prefetch_l2(lpb + 2u * HW,  4096u);
            bulk_prefetch_l2(lpb + 3u * HW,  4096u);
        }

        for (unsigned v = v0; v < NVEC; v += stride) {
            // Thread 0: bulk-prefetch next iteration's 5 chunks (20KB).
            if (threadIdx.x == 0) {
                unsigned vn = v + stride;
                if (vn < NVEC) {
                    unsigned sn  = vn << 2;
                    unsigned bn  = sn >> 18;
                    unsigned hwn = sn & (HW - 1u);
                    const float* lpn = seg_logits + (bn * 4u) * HW + hwn;
                    bulk_prefetch_l2(seg_mask + bn * HW + hwn, 4096u);
                    bulk_prefetch_l2(lpn,            4096u);
                    bulk_prefetch_l2(lpn + HW,       4096u);
                    bulk_prefetch_l2(lpn + 2u * HW,  4096u);
                    bulk_prefetch_l2(lpn + 3u * HW,  4096u);
                }
            }

            unsigned s  = v << 2;
            unsigned b  = s >> 18;
            unsigned hw = s & (HW - 1u);

            // demand loads (streaming, read-once; L2-hits thanks to prefetch)
            int4 m = __ldcs(reinterpret_cast<const int4*>(seg_mask + b * HW + hw));
            const float* lp = seg_logits + (b * 4u) * HW + hw;
            float4 x0 = __ldcs(reinterpret_cast<const float4*>(lp));
            float4 x1 = __ldcs(reinterpret_cast<const float4*>(lp + HW));
            float4 x2 = __ldcs(reinterpret_cast<const float4*>(lp + 2u * HW));
            float4 x3 = __ldcs(reinterpret_cast<const float4*>(lp + 3u * HW));

            float hy0 = 0.5f - (float)m.x;
            float hy1 = 0.5f - (float)m.y;
            float hy2 = 0.5f - (float)m.z;
            float hy3 = 0.5f - (float)m.w;

            seg_channel(x0, hy0, hy1, hy2, hy3, C3, C2, C1, C0, acc_s, acc2a, acc2b);
            seg_channel(x1, hy0, hy1, hy2, hy3, C3, C2, C1, C0, acc_s, acc2a, acc2b);
            seg_channel(x2, hy0, hy1, hy2, hy3, C3, C2, C1, C0, acc_s, acc2a, acc2b);
            seg_channel(x3, hy0, hy1, hy2, hy3, C3, C2, C1, C0, acc_s, acc2a, acc2b);
        }

        u64 acc2 = add2(acc2a, acc2b);
        float plo, phi;
        unpack2(acc2, plo, phi);
        float acc = acc_s + (plo + phi);

        float bs = block_reduce(acc, sh);
        if (threadIdx.x == 0) atomicAdd(&g_seg, (double)bs);
    }

    // ---- last-block finalize + reset ----
    __shared__ int is_last;
    if (threadIdx.x == 0) {
        __threadfence();
        unsigned old = atomicAdd(&g_count, 1u);
        is_last = (old == (unsigned)(gridDim.x - 1)) ? 1 : 0;
    }
    __syncthreads();
    if (is_last) {
        const int i = threadIdx.x;
        float v = 0.0f;
        if (i < 96) {
            int s = i >> 5, b = i & 31;
            const int Ls = (s == 0) ? 4096 : (s == 1) ? 1024 : 256;
            float cs = g_det[s][b][0];
            float rs = g_det[s][b][1];
            float ce = g_det[s][b][2];
            float np = g_det[s][b][3];
            float cls_l = cs / (float)(Ls * 4);
            float reg_l = (np > 0.0f) ? rs / np : 0.0f;
            float cen_l = (np > 0.0f) ? ce / np : 0.0f;
            v = cls_l + reg_l + cen_l;
        }
        double seg_v = g_seg;
        float  cls_v = g_cls;
        __syncthreads();                  // all reads done before reset
        float det_tot = block_reduce(v, sh);

        __shared__ float res;
        if (i == 0) {
            double total = seg_v / (32.0 * 4.0 * 512.0 * 512.0)
                         + (double)det_tot / (3.0 * 32.0)
                         + 0.5 * (double)cls_v / 320.0;
            res = (float)total;
            g_seg = 0.0; g_cls = 0.0f; g_count = 0u;
        }
        for (int k = i; k < 3 * 32 * 4; k += blockDim.x)
            (&g_det[0][0][0])[k] = 0.0f;
        __syncthreads();
        for (int k = i; k < out_n; k += blockDim.x) out[k] = res;
    }
}

// ---------------------------------------------------------------------------
// Launch: single kernel node.
// ---------------------------------------------------------------------------
extern "C" void kernel_launch(void* const* d_in, const int* in_sizes, int n_in,
                              void* d_out, int out_size) {
    main_kernel<<<TOTAL_BLOCKS, 256>>>(
        (const float*)d_in[0],  (const int*)d_in[1],
        (const float*)d_in[2],  (const float*)d_in[3],  (const float*)d_in[4],
        (const float*)d_in[5],  (const float*)d_in[6],  (const float*)d_in[7],
        (const float*)d_in[8],  (const float*)d_in[9],  (const float*)d_in[10],
        (const float*)d_in[11], (const int*)d_in[12],
        (const float*)d_in[13], (const int*)d_in[14],
        (float*)d_out, out_size);
}